// round 15
// baseline (speedup 1.0000x reference)
#include <cuda_runtime.h>
#include <cuda_fp16.h>
#include <math.h>
#include <stdint.h>

#define NN 32768
#define EE 524288
#define FF 32
#define HH 512
#define CC 10
#define GG 64

typedef __half fp16;

// ---------------- scratch ----------------------------------------------------
__device__ __align__(128) fp16 g_A0a[NN * 128], g_A0l[NN * 128];
__device__ __align__(128) fp16 g_A1a[NN * 1024], g_A1l[NN * 1024];
__device__ __align__(128) fp16 g_A2a[NN * 1024], g_A2l[NN * 1024];
__device__ __align__(128) fp16 g_B0[HH * 128];
__device__ __align__(128) fp16 g_Bw[4 * HH * 1024];
__device__ int   g_rowptr[NN + 1];
__device__ int   g_cursor[NN];
__device__ int   g_cnt[NN];
__device__ int   g_colsrc[EE];
__device__ int   g_grow[GG + 1];
__device__ int   g_gcnt[GG];
__device__ float g_feat[GG * 2 * HH];
__device__ float g_m1[GG * HH];
__device__ float g_m2[GG * HH];

// ---------------- helpers ----------------------------------------------------
__device__ __forceinline__ uint32_t smem_u32(const void* p) {
    uint32_t r;
    asm("{ .reg .u64 t; cvta.to.shared.u64 t, %1; cvt.u32.u64 %0, t; }" : "=r"(r) : "l"(p));
    return r;
}
__device__ __forceinline__ void cpa16(uint32_t d, const void* s) {
    asm volatile("cp.async.cg.shared.global [%0], [%1], 16;" :: "r"(d), "l"(s));
}
#define CP_COMMIT() asm volatile("cp.async.commit_group;" ::: "memory")
__device__ __forceinline__ void ldsm4(uint32_t* r, uint32_t a) {
    asm volatile("ldmatrix.sync.aligned.m8n8.x4.shared.b16 {%0,%1,%2,%3}, [%4];"
                 : "=r"(r[0]), "=r"(r[1]), "=r"(r[2]), "=r"(r[3]) : "r"(a));
}
__device__ __forceinline__ void mma_fp16(float* c, const uint32_t* a, const uint32_t* b) {
    asm volatile("mma.sync.aligned.m16n8k16.row.col.f32.f16.f16.f32 "
                 "{%0,%1,%2,%3}, {%4,%5,%6,%7}, {%8,%9}, {%0,%1,%2,%3};"
                 : "+f"(c[0]), "+f"(c[1]), "+f"(c[2]), "+f"(c[3])
                 : "r"(a[0]), "r"(a[1]), "r"(a[2]), "r"(a[3]), "r"(b[0]), "r"(b[1]));
}
__device__ __forceinline__ void split_fp16(float v, fp16& hi, fp16& lo) {
    hi = __float2half_rn(v);
    lo = __float2half_rn(v - __half2float(hi));
}
__device__ __forceinline__ uint32_t swz(uint32_t off) { return off ^ ((off >> 3) & 0x70); }

// ---------------- CSR build --------------------------------------------------
__global__ void k_zero_counts() {
    int i = blockIdx.x * blockDim.x + threadIdx.x;
    if (i < NN) g_cnt[i] = 0;
    if (i < GG) g_gcnt[i] = 0;
}
__global__ void k_hist(const int* __restrict__ ei, const int* __restrict__ batch) {
    int e = blockIdx.x * blockDim.x + threadIdx.x;
    if (e < EE) atomicAdd(&g_cnt[ei[EE + e]], 1);
    if (e < NN) atomicAdd(&g_gcnt[batch[e]], 1);
}
__global__ void k_scan() {
    __shared__ int sums[1024];
    const int per = NN / 1024;
    int tid = threadIdx.x, base = tid * per;
    int local[32];
    int s = 0;
    for (int i = 0; i < per; i++) { local[i] = s; s += g_cnt[base + i]; }
    sums[tid] = s;
    __syncthreads();
    for (int off = 1; off < 1024; off <<= 1) {
        int v = (tid >= off) ? sums[tid - off] : 0;
        __syncthreads();
        sums[tid] += v;
        __syncthreads();
    }
    int excl = (tid == 0) ? 0 : sums[tid - 1];
    for (int i = 0; i < per; i++) {
        int v = excl + local[i];
        g_rowptr[base + i] = v;
        g_cursor[base + i] = v;
    }
    if (tid == 1023) g_rowptr[NN] = sums[1023];
    if (tid == 0) {
        int t = 0;
        for (int g = 0; g < GG; g++) { g_grow[g] = t; t += g_gcnt[g]; }
        g_grow[GG] = t;
    }
}
__global__ void k_fill(const int* __restrict__ ei) {
    int e = blockIdx.x * blockDim.x + threadIdx.x;
    if (e >= EE) return;
    int p = atomicAdd(&g_cursor[ei[EE + e]], 1);
    g_colsrc[p] = ei[e];
}
__global__ void k_sortadj() {
    int v = blockIdx.x * blockDim.x + threadIdx.x;
    if (v >= NN) return;
    int s = g_rowptr[v], e = g_rowptr[v + 1];
    for (int i = s + 1; i < e; i++) {
        int key = g_colsrc[i];
        int j = i - 1;
        while (j >= s && g_colsrc[j] > key) { g_colsrc[j + 1] = g_colsrc[j]; j--; }
        g_colsrc[j + 1] = key;
    }
}

// ---------------- split prep -------------------------------------------------
__global__ void k_split_x(const float* __restrict__ x) {
    int i = blockIdx.x * blockDim.x + threadIdx.x;
    if (i >= NN * 64) return;
    int r = i >> 6, k = i & 63;
    float v = (k < FF) ? x[r * FF + k] : 0.f;
    fp16 hi, lo;
    split_fp16(v, hi, lo);
    g_A0a[r * 128 + k] = hi;
    g_A0l[r * 128 + k] = lo;
}
__global__ void k_split_w0(const float* __restrict__ wr, const float* __restrict__ ws) {
    int i = blockIdx.x * blockDim.x + threadIdx.x;
    if (i >= HH * 128) return;
    int n = i >> 7, k = i & 127;
    float v = 0.f;
    if (k < FF) v = wr[k * HH + n];
    else if (k >= 64 && k < 64 + FF) v = ws[(k - 64) * HH + n];
    g_B0[i] = __float2half_rn(v);
}
__global__ void k_split_w(const float* __restrict__ wr, const float* __restrict__ ws) {
    int i = blockIdx.x * blockDim.x + threadIdx.x;
    if (i >= 4 * HH * 1024) return;
    int l = i >> 19;
    int rem = i & ((1 << 19) - 1);
    int n = rem >> 10, k = rem & 1023;
    float v = (k < HH) ? wr[(size_t)l * HH * HH + (size_t)k * HH + n]
                       : ws[(size_t)l * HH * HH + (size_t)(k - HH) * HH + n];
    g_Bw[i] = __float2half_rn(v);
}

// ---------------- aggregation (MLP=2, R13-proven) -----------------------------
__global__ void k_agg32(const float* __restrict__ x) {
    int v = blockIdx.x * 4 + threadIdx.y;
    int lane = threadIdx.x;
    if (v >= NN) return;
    int s = g_rowptr[v], e = g_rowptr[v + 1];
    float acc0 = 0.f, acc1 = 0.f;
    int i = s;
    for (; i + 1 < e; i += 2) {
        acc0 += x[g_colsrc[i] * FF + lane];
        acc1 += x[g_colsrc[i + 1] * FF + lane];
    }
    if (i < e) acc0 += x[g_colsrc[i] * FF + lane];
    float acc = acc0 + acc1;
    fp16 hi, lo;
    split_fp16(acc, hi, lo);
    g_A0a[v * 128 + 64 + lane] = hi;
    g_A0l[v * 128 + 64 + lane] = lo;
    g_A0a[v * 128 + 96 + lane] = __float2half(0.f);
    g_A0l[v * 128 + 96 + lane] = __float2half(0.f);
}
__global__ void k_agg512(fp16* __restrict__ aa, fp16* __restrict__ al) {
    int v = blockIdx.x, tx = threadIdx.x;
    int s = g_rowptr[v], e = g_rowptr[v + 1];
    float p0[4] = {0.f, 0.f, 0.f, 0.f};
    float p1[4] = {0.f, 0.f, 0.f, 0.f};
    int i = s;
    for (; i + 1 < e; i += 2) {
        uint2 t0 = *(const uint2*)&aa[(size_t)g_colsrc[i] * 1024 + tx * 4];
        uint2 t1 = *(const uint2*)&aa[(size_t)g_colsrc[i + 1] * 1024 + tx * 4];
        float2 a = __half22float2(*(__half2*)&t0.x);
        float2 b = __half22float2(*(__half2*)&t0.y);
        float2 c = __half22float2(*(__half2*)&t1.x);
        float2 d = __half22float2(*(__half2*)&t1.y);
        p0[0] += a.x; p0[1] += a.y; p0[2] += b.x; p0[3] += b.y;
        p1[0] += c.x; p1[1] += c.y; p1[2] += d.x; p1[3] += d.y;
    }
    if (i < e) {
        uint2 t0 = *(const uint2*)&aa[(size_t)g_colsrc[i] * 1024 + tx * 4];
        float2 a = __half22float2(*(__half2*)&t0.x);
        float2 b = __half22float2(*(__half2*)&t0.y);
        p0[0] += a.x; p0[1] += a.y; p0[2] += b.x; p0[3] += b.y;
    }
    fp16 hi[4], lo[4];
#pragma unroll
    for (int j = 0; j < 4; j++) split_fp16(p0[j] + p1[j], hi[j], lo[j]);
    *(uint2*)&aa[(size_t)v * 1024 + 512 + tx * 4] = *(uint2*)hi;
    *(uint2*)&al[(size_t)v * 1024 + 512 + tx * 4] = *(uint2*)lo;
}

// ---------------- fp16 mma GEMM: 2 terms, K-chunk 128 -------------------------
// CTA 128m x 128n, 8 warps (2x4), warp tile 64x32, 2-stage, occ 1.
// Stage 96KB: Aah 32K | Aal 32K | Bh 32K  (each plane = two 16KB 64-col blocks).
// D = (Aah + Aal) @ Bh;  out = tanh(D + bias) -> fp16 ah/al planes.
#define STAGE_B 98304

__global__ __launch_bounds__(256, 1)
void k_mmagemm(const fp16* __restrict__ Aah, const fp16* __restrict__ Aal,
               const fp16* __restrict__ Bh,
               const float* __restrict__ bias,
               fp16* __restrict__ oa, fp16* __restrict__ ol, int Kp) {
    extern __shared__ char smem[];
    uint32_t sb = smem_u32(smem);
    const int tid = threadIdx.x;
    const int wid = tid >> 5, lane = tid & 31;
    const int brow = blockIdx.y * 128;
    const int bcol = blockIdx.x * 128;
    const int wm = (wid & 1) * 64;
    const int wn = (wid >> 1) * 32;
    const int C2 = Kp >> 7;              // number of 128-col chunks
    const int KS = (Kp >= 128) ? 8 : 4;  // ks iterations per chunk

    float acc[4][4][4];
#pragma unroll
    for (int i = 0; i < 4; i++)
#pragma unroll
        for (int j = 0; j < 4; j++)
#pragma unroll
            for (int q = 0; q < 4; q++) acc[i][j][q] = 0.f;

    auto copy_stage = [&](int buf, int cc) {
        uint32_t st = sb + (uint32_t)buf * STAGE_B;
#pragma unroll
        for (int i = 0; i < 8; i++) {
            int id = tid * 8 + i;           // 0..2047
            int sblk = id >> 10;            // 0..1  (64-col sub-block)
            int rem = id & 1023;
            int r = rem >> 3, u = rem & 7;
            uint32_t sw = swz((uint32_t)(r * 128 + u * 16)) + (uint32_t)sblk * 16384;
            int col = cc * 128 + sblk * 64 + u * 8;
            cpa16(st + sw, Aah + (size_t)(brow + r) * Kp + col);
            cpa16(st + 32768 + sw, Aal + (size_t)(brow + r) * Kp + col);
            cpa16(st + 65536 + sw, Bh + (size_t)(bcol + r) * Kp + col);
        }
        CP_COMMIT();
    };

    const int a_row = wm + ((lane >> 3) & 1) * 8 + (lane & 7);
    const int a_ub  = lane >> 4;
    const int b_row = wn + ((lane >> 4) & 1) * 8 + (lane & 7);
    const int b_ub  = (lane >> 3) & 1;

    int nC = (C2 > 0) ? C2 : 1;
    copy_stage(0, 0);

    for (int c = 0; c < nC; c++) {
        int buf = c & 1;
        if (c + 1 < nC) {
            copy_stage(buf ^ 1, c + 1);
            asm volatile("cp.async.wait_group 1;" ::: "memory");
        } else {
            asm volatile("cp.async.wait_group 0;" ::: "memory");
        }
        __syncthreads();

        uint32_t base = sb + (uint32_t)buf * STAGE_B;
#pragma unroll
        for (int ks = 0; ks < 8; ks++) {
            if (ks >= KS) break;
            uint32_t blk = (uint32_t)(ks >> 2) * 16384;
            int ku = (ks & 3) * 2;
            uint32_t ah[4][4], al[4][4], bh[2][4];
#pragma unroll
            for (int i = 0; i < 4; i++) {
                uint32_t off = blk + swz((uint32_t)((a_row + i * 16) * 128 + (ku + a_ub) * 16));
                ldsm4(ah[i], base + off);
                ldsm4(al[i], base + 32768 + off);
            }
#pragma unroll
            for (int j2 = 0; j2 < 2; j2++) {
                uint32_t off = blk + swz((uint32_t)((b_row + j2 * 16) * 128 + (ku + b_ub) * 16));
                ldsm4(bh[j2], base + 65536 + off);
            }
#pragma unroll
            for (int i = 0; i < 4; i++)
#pragma unroll
                for (int j = 0; j < 4; j++) {
                    const uint32_t* ph = &bh[j >> 1][(j & 1) * 2];
                    mma_fp16(acc[i][j], ah[i], ph);
                    mma_fp16(acc[i][j], al[i], ph);
                }
        }
        __syncthreads();
    }

    // epilogue: bias + tanh -> fp16 ah/al planes
#pragma unroll
    for (int i = 0; i < 4; i++) {
        int r0 = brow + wm + i * 16 + (lane >> 2);
#pragma unroll
        for (int j = 0; j < 4; j++) {
            int col = bcol + wn + j * 8 + (lane & 3) * 2;
            float b0v = bias[col], b1v = bias[col + 1];
            float v0 = tanhf(acc[i][j][0] + b0v);
            float v1 = tanhf(acc[i][j][1] + b1v);
            float v2 = tanhf(acc[i][j][2] + b0v);
            float v3 = tanhf(acc[i][j][3] + b1v);
            fp16 h0, l0, h1, l1;
            __half2 th, tl;
            split_fp16(v0, h0, l0); split_fp16(v1, h1, l1);
            th = __halves2half2(h0, h1); tl = __halves2half2(l0, l1);
            *(__half2*)&oa[(size_t)r0 * 1024 + col] = th;
            *(__half2*)&ol[(size_t)r0 * 1024 + col] = tl;
            split_fp16(v2, h0, l0); split_fp16(v3, h1, l1);
            th = __halves2half2(h0, h1); tl = __halves2half2(l0, l1);
            *(__half2*)&oa[(size_t)(r0 + 8) * 1024 + col] = th;
            *(__half2*)&ol[(size_t)(r0 + 8) * 1024 + col] = tl;
        }
    }
}

// ---------------- pooling / MLP / head ---------------------------------------
__global__ void k_pool(const fp16* __restrict__ ha, const fp16* __restrict__ hl) {
    int g = blockIdx.x;
    int c0 = threadIdx.x * 4;
    int s = g_grow[g], e = g_grow[g + 1];
    float mx[4] = {-INFINITY, -INFINITY, -INFINITY, -INFINITY};
    float sm[4] = {0.f, 0.f, 0.f, 0.f};
    for (int i = s; i < e; i++) {
        uint2 th = *(const uint2*)&ha[(size_t)i * 1024 + c0];
        uint2 tl = *(const uint2*)&hl[(size_t)i * 1024 + c0];
        float2 ah0 = __half22float2(*(__half2*)&th.x);
        float2 ah1 = __half22float2(*(__half2*)&th.y);
        float2 al0 = __half22float2(*(__half2*)&tl.x);
        float2 al1 = __half22float2(*(__half2*)&tl.y);
        float v0 = ah0.x + al0.x, v1 = ah0.y + al0.y;
        float v2 = ah1.x + al1.x, v3 = ah1.y + al1.y;
        mx[0] = fmaxf(mx[0], v0); sm[0] += v0;
        mx[1] = fmaxf(mx[1], v1); sm[1] += v1;
        mx[2] = fmaxf(mx[2], v2); sm[2] += v2;
        mx[3] = fmaxf(mx[3], v3); sm[3] += v3;
    }
    float inv = 1.f / fmaxf((float)(e - s), 1.f);
#pragma unroll
    for (int q = 0; q < 4; q++) {
        g_feat[g * 2 * HH + c0 + q]      = mx[q];
        g_feat[g * 2 * HH + HH + c0 + q] = sm[q] * inv;
    }
}
__global__ void k_mlp(const float* __restrict__ A, const float* __restrict__ W,
                      const float* __restrict__ b, float* __restrict__ out,
                      int K, int Nn) {
    int n = blockIdx.x * blockDim.x + threadIdx.x;
    int m = blockIdx.y;
    float s = b[n];
    for (int k = 0; k < K; k++) s += A[m * K + k] * W[k * Nn + n];
    out[m * Nn + n] = tanhf(s);
}
__global__ void k_head(const float* __restrict__ A, const float* __restrict__ W,
                       const float* __restrict__ b, float* __restrict__ out) {
    int g = blockIdx.x;
    int lane = threadIdx.x;
    float cls[CC];
#pragma unroll
    for (int c = 0; c < CC; c++) {
        float s = 0.f;
        for (int k = lane; k < HH; k += 32) s += A[g * HH + k] * W[k * CC + c];
#pragma unroll
        for (int off = 16; off; off >>= 1) s += __shfl_xor_sync(0xffffffffu, s, off);
        cls[c] = s + b[c];
    }
    float mx = -INFINITY;
#pragma unroll
    for (int c = 0; c < CC; c++) mx = fmaxf(mx, cls[c]);
    float se = 0.f;
#pragma unroll
    for (int c = 0; c < CC; c++) se += expf(cls[c] - mx);
    float lse = mx + logf(se);
    if (lane < CC) out[g * CC + lane] = cls[lane] - lse;
}

// ---------------- launcher ---------------------------------------------------
extern "C" void kernel_launch(void* const* d_in, const int* in_sizes, int n_in,
                              void* d_out, int out_size) {
    const float* x       = (const float*)d_in[0];
    const int*   ei      = (const int*)  d_in[1];
    const int*   batch   = (const int*)  d_in[2];
    const float* w_root0 = (const float*)d_in[3];
    const float* w_rel0  = (const float*)d_in[4];
    const float* b0      = (const float*)d_in[5];
    const float* w_root  = (const float*)d_in[6];
    const float* w_rel   = (const float*)d_in[7];
    const float* bb      = (const float*)d_in[8];
    const float* lin1_w  = (const float*)d_in[9];
    const float* lin1_b  = (const float*)d_in[10];
    const float* lin2_w  = (const float*)d_in[11];
    const float* lin2_b  = (const float*)d_in[12];
    const float* lin3_w  = (const float*)d_in[13];
    const float* lin3_b  = (const float*)d_in[14];
    float* out = (float*)d_out;

    float *feat, *m1, *m2;
    fp16 *a0a, *a0l, *a1a, *a1l, *a2a, *a2l, *b0p, *bwp;
    cudaGetSymbolAddress((void**)&feat, g_feat);
    cudaGetSymbolAddress((void**)&m1, g_m1);
    cudaGetSymbolAddress((void**)&m2, g_m2);
    cudaGetSymbolAddress((void**)&a0a, g_A0a);
    cudaGetSymbolAddress((void**)&a0l, g_A0l);
    cudaGetSymbolAddress((void**)&a1a, g_A1a);
    cudaGetSymbolAddress((void**)&a1l, g_A1l);
    cudaGetSymbolAddress((void**)&a2a, g_A2a);
    cudaGetSymbolAddress((void**)&a2l, g_A2l);
    cudaGetSymbolAddress((void**)&b0p, g_B0);
    cudaGetSymbolAddress((void**)&bwp, g_Bw);

    cudaFuncSetAttribute(k_mmagemm, cudaFuncAttributeMaxDynamicSharedMemorySize,
                         2 * STAGE_B);
    const int dynsmem = 2 * STAGE_B;

    // CSR + graph segments
    k_zero_counts<<<(NN + 255) / 256, 256>>>();
    k_hist<<<(EE + 255) / 256, 256>>>(ei, batch);
    k_scan<<<1, 1024>>>();
    k_fill<<<(EE + 255) / 256, 256>>>(ei);
    k_sortadj<<<(NN + 127) / 128, 128>>>();

    // prep splits
    k_split_x<<<(NN * 64 + 255) / 256, 256>>>(x);
    k_split_w0<<<(HH * 128 + 255) / 256, 256>>>(w_root0, w_rel0);
    k_split_w<<<(4 * HH * 1024 + 255) / 256, 256>>>(w_root, w_rel);

    // layer 0: K'=128 (single chunk)
    k_agg32<<<NN / 4, dim3(32, 4)>>>(x);
    k_mmagemm<<<dim3(HH / 128, NN / 128), 256, dynsmem>>>(
        a0a, a0l, b0p, b0, a1a, a1l, 128);

    // layers 1..4: K'=1024, ping-pong buf1/buf2
    fp16 *aca = a1a, *acl = a1l, *ana = a2a, *anl = a2l;
    for (int l = 0; l < 4; l++) {
        k_agg512<<<NN, 128>>>(aca, acl);
        k_mmagemm<<<dim3(HH / 128, NN / 128), 256, dynsmem>>>(
            aca, acl, bwp + (size_t)l * HH * 1024,
            bb + l * HH, ana, anl, 1024);
        fp16* t1 = aca; aca = ana; ana = t1;
        fp16* t2 = acl; acl = anl; anl = t2;
    }

    k_pool<<<GG, 128>>>(aca, acl);
    k_mlp<<<dim3(HH / 128, GG), 128>>>(feat, lin1_w, lin1_b, m1, 2 * HH, HH);
    k_mlp<<<dim3(HH / 128, GG), 128>>>(m1, lin2_w, lin2_b, m2, HH, HH);
    k_head<<<GG, 32>>>(m2, lin3_w, lin3_b, out);
}

// round 16
// speedup vs baseline: 1.3201x; 1.3201x over previous
#include <cuda_runtime.h>
#include <cuda_fp16.h>
#include <math.h>
#include <stdint.h>

#define NN 32768
#define EE 524288
#define FF 32
#define HH 512
#define CC 10
#define GG 64

typedef __half fp16;

// ---------------- scratch ----------------------------------------------------
__device__ __align__(128) fp16 g_A0a[NN * 128], g_A0l[NN * 128];
__device__ __align__(128) fp16 g_A1a[NN * 1024], g_A1l[NN * 1024];
__device__ __align__(128) fp16 g_A2a[NN * 1024], g_A2l[NN * 1024];
__device__ __align__(128) fp16 g_B0[HH * 128];
__device__ __align__(128) fp16 g_Bw[4 * HH * 1024];
__device__ int   g_rowptr[NN + 1];
__device__ int   g_cursor[NN];
__device__ int   g_cnt[NN];
__device__ int   g_colsrc[EE];
__device__ int   g_grow[GG + 1];
__device__ int   g_gcnt[GG];
__device__ float g_feat[GG * 2 * HH];
__device__ float g_m1[GG * HH];
__device__ float g_m2[GG * HH];

// ---------------- helpers ----------------------------------------------------
__device__ __forceinline__ uint32_t smem_u32(const void* p) {
    uint32_t r;
    asm("{ .reg .u64 t; cvta.to.shared.u64 t, %1; cvt.u32.u64 %0, t; }" : "=r"(r) : "l"(p));
    return r;
}
__device__ __forceinline__ void cpa16(uint32_t d, const void* s) {
    asm volatile("cp.async.cg.shared.global [%0], [%1], 16;" :: "r"(d), "l"(s));
}
#define CP_COMMIT() asm volatile("cp.async.commit_group;" ::: "memory")
__device__ __forceinline__ void ldsm4(uint32_t* r, uint32_t a) {
    asm volatile("ldmatrix.sync.aligned.m8n8.x4.shared.b16 {%0,%1,%2,%3}, [%4];"
                 : "=r"(r[0]), "=r"(r[1]), "=r"(r[2]), "=r"(r[3]) : "r"(a));
}
__device__ __forceinline__ void mma_fp16(float* c, const uint32_t* a, const uint32_t* b) {
    asm volatile("mma.sync.aligned.m16n8k16.row.col.f32.f16.f16.f32 "
                 "{%0,%1,%2,%3}, {%4,%5,%6,%7}, {%8,%9}, {%0,%1,%2,%3};"
                 : "+f"(c[0]), "+f"(c[1]), "+f"(c[2]), "+f"(c[3])
                 : "r"(a[0]), "r"(a[1]), "r"(a[2]), "r"(a[3]), "r"(b[0]), "r"(b[1]));
}
__device__ __forceinline__ void split_fp16(float v, fp16& hi, fp16& lo) {
    hi = __float2half_rn(v);
    lo = __float2half_rn(v - __half2float(hi));
}
__device__ __forceinline__ uint32_t swz(uint32_t off) { return off ^ ((off >> 3) & 0x70); }

// ---------------- CSR build --------------------------------------------------
__global__ void k_zero_counts() {
    int i = blockIdx.x * blockDim.x + threadIdx.x;
    if (i < NN) g_cnt[i] = 0;
    if (i < GG) g_gcnt[i] = 0;
}
__global__ void k_hist(const int* __restrict__ ei, const int* __restrict__ batch) {
    int e = blockIdx.x * blockDim.x + threadIdx.x;
    if (e < EE) atomicAdd(&g_cnt[ei[EE + e]], 1);
    if (e < NN) atomicAdd(&g_gcnt[batch[e]], 1);
}
__global__ void k_scan() {
    __shared__ int sums[1024];
    const int per = NN / 1024;
    int tid = threadIdx.x, base = tid * per;
    int local[32];
    int s = 0;
    for (int i = 0; i < per; i++) { local[i] = s; s += g_cnt[base + i]; }
    sums[tid] = s;
    __syncthreads();
    for (int off = 1; off < 1024; off <<= 1) {
        int v = (tid >= off) ? sums[tid - off] : 0;
        __syncthreads();
        sums[tid] += v;
        __syncthreads();
    }
    int excl = (tid == 0) ? 0 : sums[tid - 1];
    for (int i = 0; i < per; i++) {
        int v = excl + local[i];
        g_rowptr[base + i] = v;
        g_cursor[base + i] = v;
    }
    if (tid == 1023) g_rowptr[NN] = sums[1023];
    if (tid == 0) {
        int t = 0;
        for (int g = 0; g < GG; g++) { g_grow[g] = t; t += g_gcnt[g]; }
        g_grow[GG] = t;
    }
}
__global__ void k_fill(const int* __restrict__ ei) {
    int e = blockIdx.x * blockDim.x + threadIdx.x;
    if (e >= EE) return;
    int p = atomicAdd(&g_cursor[ei[EE + e]], 1);
    g_colsrc[p] = ei[e];
}
__global__ void k_sortadj() {
    int v = blockIdx.x * blockDim.x + threadIdx.x;
    if (v >= NN) return;
    int s = g_rowptr[v], e = g_rowptr[v + 1];
    for (int i = s + 1; i < e; i++) {
        int key = g_colsrc[i];
        int j = i - 1;
        while (j >= s && g_colsrc[j] > key) { g_colsrc[j + 1] = g_colsrc[j]; j--; }
        g_colsrc[j + 1] = key;
    }
}

// ---------------- split prep -------------------------------------------------
__global__ void k_split_x(const float* __restrict__ x) {
    int i = blockIdx.x * blockDim.x + threadIdx.x;
    if (i >= NN * 64) return;
    int r = i >> 6, k = i & 63;
    float v = (k < FF) ? x[r * FF + k] : 0.f;
    fp16 hi, lo;
    split_fp16(v, hi, lo);
    g_A0a[r * 128 + k] = hi;
    g_A0l[r * 128 + k] = lo;
}
__global__ void k_split_w0(const float* __restrict__ wr, const float* __restrict__ ws) {
    int i = blockIdx.x * blockDim.x + threadIdx.x;
    if (i >= HH * 128) return;
    int n = i >> 7, k = i & 127;
    float v = 0.f;
    if (k < FF) v = wr[k * HH + n];
    else if (k >= 64 && k < 64 + FF) v = ws[(k - 64) * HH + n];
    g_B0[i] = __float2half_rn(v);
}
__global__ void k_split_w(const float* __restrict__ wr, const float* __restrict__ ws) {
    int i = blockIdx.x * blockDim.x + threadIdx.x;
    if (i >= 4 * HH * 1024) return;
    int l = i >> 19;
    int rem = i & ((1 << 19) - 1);
    int n = rem >> 10, k = rem & 1023;
    float v = (k < HH) ? wr[(size_t)l * HH * HH + (size_t)k * HH + n]
                       : ws[(size_t)l * HH * HH + (size_t)(k - HH) * HH + n];
    g_Bw[i] = __float2half_rn(v);
}

// ---------------- aggregation (MLP=2, R13-proven) -----------------------------
__global__ void k_agg32(const float* __restrict__ x) {
    int v = blockIdx.x * 4 + threadIdx.y;
    int lane = threadIdx.x;
    if (v >= NN) return;
    int s = g_rowptr[v], e = g_rowptr[v + 1];
    float acc0 = 0.f, acc1 = 0.f;
    int i = s;
    for (; i + 1 < e; i += 2) {
        acc0 += x[g_colsrc[i] * FF + lane];
        acc1 += x[g_colsrc[i + 1] * FF + lane];
    }
    if (i < e) acc0 += x[g_colsrc[i] * FF + lane];
    float acc = acc0 + acc1;
    fp16 hi, lo;
    split_fp16(acc, hi, lo);
    g_A0a[v * 128 + 64 + lane] = hi;
    g_A0l[v * 128 + 64 + lane] = lo;
    g_A0a[v * 128 + 96 + lane] = __float2half(0.f);
    g_A0l[v * 128 + 96 + lane] = __float2half(0.f);
}
__global__ void k_agg512(fp16* __restrict__ aa, fp16* __restrict__ al) {
    int v = blockIdx.x, tx = threadIdx.x;
    int s = g_rowptr[v], e = g_rowptr[v + 1];
    float p0[4] = {0.f, 0.f, 0.f, 0.f};
    float p1[4] = {0.f, 0.f, 0.f, 0.f};
    int i = s;
    for (; i + 1 < e; i += 2) {
        uint2 t0 = *(const uint2*)&aa[(size_t)g_colsrc[i] * 1024 + tx * 4];
        uint2 t1 = *(const uint2*)&aa[(size_t)g_colsrc[i + 1] * 1024 + tx * 4];
        float2 a = __half22float2(*(__half2*)&t0.x);
        float2 b = __half22float2(*(__half2*)&t0.y);
        float2 c = __half22float2(*(__half2*)&t1.x);
        float2 d = __half22float2(*(__half2*)&t1.y);
        p0[0] += a.x; p0[1] += a.y; p0[2] += b.x; p0[3] += b.y;
        p1[0] += c.x; p1[1] += c.y; p1[2] += d.x; p1[3] += d.y;
    }
    if (i < e) {
        uint2 t0 = *(const uint2*)&aa[(size_t)g_colsrc[i] * 1024 + tx * 4];
        float2 a = __half22float2(*(__half2*)&t0.x);
        float2 b = __half22float2(*(__half2*)&t0.y);
        p0[0] += a.x; p0[1] += a.y; p0[2] += b.x; p0[3] += b.y;
    }
    fp16 hi[4], lo[4];
#pragma unroll
    for (int j = 0; j < 4; j++) split_fp16(p0[j] + p1[j], hi[j], lo[j]);
    *(uint2*)&aa[(size_t)v * 1024 + 512 + tx * 4] = *(uint2*)hi;
    *(uint2*)&al[(size_t)v * 1024 + 512 + tx * 4] = *(uint2*)lo;
}

// ---------------- fp16 mma GEMM: 2 terms, occ 2, per-i fragment loading -------
// CTA 128m x 128n, 8 warps (2x4), warp tile 64x32, BK=64, 2-stage.
// Stage 48KB: Aah 16K | Aal 16K | Bh 16K.  96KB x occ2 = 192KB/SM.
// Inner: per ks load bh(8 regs); per i load ah,al (8 regs) -> 8 mma. ~100 regs.
#define STAGE_B 49152

__global__ __launch_bounds__(256, 2)
void k_mmagemm(const fp16* __restrict__ Aah, const fp16* __restrict__ Aal,
               const fp16* __restrict__ Bh,
               const float* __restrict__ bias,
               fp16* __restrict__ oa, fp16* __restrict__ ol, int Kp) {
    extern __shared__ char smem[];
    uint32_t sb = smem_u32(smem);
    const int tid = threadIdx.x;
    const int wid = tid >> 5, lane = tid & 31;
    const int brow = blockIdx.y * 128;
    const int bcol = blockIdx.x * 128;
    const int wm = (wid & 1) * 64;
    const int wn = (wid >> 1) * 32;
    const int C = Kp >> 6;

    float acc[4][4][4];
#pragma unroll
    for (int i = 0; i < 4; i++)
#pragma unroll
        for (int j = 0; j < 4; j++)
#pragma unroll
            for (int q = 0; q < 4; q++) acc[i][j][q] = 0.f;

    auto copy_stage = [&](int buf, int c) {
        uint32_t st = sb + (uint32_t)buf * STAGE_B;
#pragma unroll
        for (int i = 0; i < 4; i++) {
            int id = tid * 4 + i;
            int r = id >> 3, u = id & 7;
            uint32_t sw = swz((uint32_t)(r * 128 + u * 16));
            cpa16(st + sw, Aah + (size_t)(brow + r) * Kp + c * 64 + u * 8);
            cpa16(st + 16384 + sw, Aal + (size_t)(brow + r) * Kp + c * 64 + u * 8);
            cpa16(st + 32768 + sw, Bh + (size_t)(bcol + r) * Kp + c * 64 + u * 8);
        }
        CP_COMMIT();
    };

    const int a_row = wm + ((lane >> 3) & 1) * 8 + (lane & 7);
    const int a_ub  = lane >> 4;
    const int b_row = wn + ((lane >> 4) & 1) * 8 + (lane & 7);
    const int b_ub  = (lane >> 3) & 1;

    copy_stage(0, 0);

    for (int c = 0; c < C; c++) {
        int buf = c & 1;
        if (c + 1 < C) {
            copy_stage(buf ^ 1, c + 1);
            asm volatile("cp.async.wait_group 1;" ::: "memory");
        } else {
            asm volatile("cp.async.wait_group 0;" ::: "memory");
        }
        __syncthreads();

        uint32_t base = sb + (uint32_t)buf * STAGE_B;
#pragma unroll
        for (int ks = 0; ks < 4; ks++) {
            int ku = ks * 2;
            uint32_t bh[2][4];
#pragma unroll
            for (int j2 = 0; j2 < 2; j2++) {
                uint32_t off = swz((uint32_t)((b_row + j2 * 16) * 128 + (ku + b_ub) * 16));
                ldsm4(bh[j2], base + 32768 + off);
            }
#pragma unroll
            for (int i = 0; i < 4; i++) {
                uint32_t ah[4], al[4];
                uint32_t off = swz((uint32_t)((a_row + i * 16) * 128 + (ku + a_ub) * 16));
                ldsm4(ah, base + off);
                ldsm4(al, base + 16384 + off);
#pragma unroll
                for (int j = 0; j < 4; j++) {
                    const uint32_t* ph = &bh[j >> 1][(j & 1) * 2];
                    mma_fp16(acc[i][j], ah, ph);
                    mma_fp16(acc[i][j], al, ph);
                }
            }
        }
        __syncthreads();
    }

    // epilogue: bias + tanh -> fp16 ah/al planes
#pragma unroll
    for (int i = 0; i < 4; i++) {
        int r0 = brow + wm + i * 16 + (lane >> 2);
#pragma unroll
        for (int j = 0; j < 4; j++) {
            int col = bcol + wn + j * 8 + (lane & 3) * 2;
            float b0v = bias[col], b1v = bias[col + 1];
            float v0 = tanhf(acc[i][j][0] + b0v);
            float v1 = tanhf(acc[i][j][1] + b1v);
            float v2 = tanhf(acc[i][j][2] + b0v);
            float v3 = tanhf(acc[i][j][3] + b1v);
            fp16 h0, l0, h1, l1;
            __half2 th, tl;
            split_fp16(v0, h0, l0); split_fp16(v1, h1, l1);
            th = __halves2half2(h0, h1); tl = __halves2half2(l0, l1);
            *(__half2*)&oa[(size_t)r0 * 1024 + col] = th;
            *(__half2*)&ol[(size_t)r0 * 1024 + col] = tl;
            split_fp16(v2, h0, l0); split_fp16(v3, h1, l1);
            th = __halves2half2(h0, h1); tl = __halves2half2(l0, l1);
            *(__half2*)&oa[(size_t)(r0 + 8) * 1024 + col] = th;
            *(__half2*)&ol[(size_t)(r0 + 8) * 1024 + col] = tl;
        }
    }
}

// ---------------- pooling / MLP / head ---------------------------------------
__global__ void k_pool(const fp16* __restrict__ ha, const fp16* __restrict__ hl) {
    int g = blockIdx.x;
    int c = blockIdx.y * 128 + threadIdx.x;
    int s = g_grow[g], e = g_grow[g + 1];
    float mx = -INFINITY, sm = 0.f;
    for (int i = s; i < e; i++) {
        float v = __half2float(ha[(size_t)i * 1024 + c]) +
                  __half2float(hl[(size_t)i * 1024 + c]);
        mx = fmaxf(mx, v);
        sm += v;
    }
    g_feat[g * 2 * HH + c]      = mx;
    g_feat[g * 2 * HH + HH + c] = sm / fmaxf((float)(e - s), 1.f);
}
__global__ void k_mlp(const float* __restrict__ A, const float* __restrict__ W,
                      const float* __restrict__ b, float* __restrict__ out,
                      int K, int Nn) {
    int n = blockIdx.x * blockDim.x + threadIdx.x;
    int m = blockIdx.y;
    float s = b[n];
    for (int k = 0; k < K; k++) s += A[m * K + k] * W[k * Nn + n];
    out[m * Nn + n] = tanhf(s);
}
__global__ void k_head(const float* __restrict__ A, const float* __restrict__ W,
                       const float* __restrict__ b, float* __restrict__ out) {
    int g = blockIdx.x;
    int lane = threadIdx.x;
    float cls[CC];
#pragma unroll
    for (int c = 0; c < CC; c++) {
        float s = 0.f;
        for (int k = lane; k < HH; k += 32) s += A[g * HH + k] * W[k * CC + c];
#pragma unroll
        for (int off = 16; off; off >>= 1) s += __shfl_xor_sync(0xffffffffu, s, off);
        cls[c] = s + b[c];
    }
    float mx = -INFINITY;
#pragma unroll
    for (int c = 0; c < CC; c++) mx = fmaxf(mx, cls[c]);
    float se = 0.f;
#pragma unroll
    for (int c = 0; c < CC; c++) se += expf(cls[c] - mx);
    float lse = mx + logf(se);
    if (lane < CC) out[g * CC + lane] = cls[lane] - lse;
}

// ---------------- launcher ---------------------------------------------------
extern "C" void kernel_launch(void* const* d_in, const int* in_sizes, int n_in,
                              void* d_out, int out_size) {
    const float* x       = (const float*)d_in[0];
    const int*   ei      = (const int*)  d_in[1];
    const int*   batch   = (const int*)  d_in[2];
    const float* w_root0 = (const float*)d_in[3];
    const float* w_rel0  = (const float*)d_in[4];
    const float* b0      = (const float*)d_in[5];
    const float* w_root  = (const float*)d_in[6];
    const float* w_rel   = (const float*)d_in[7];
    const float* bb      = (const float*)d_in[8];
    const float* lin1_w  = (const float*)d_in[9];
    const float* lin1_b  = (const float*)d_in[10];
    const float* lin2_w  = (const float*)d_in[11];
    const float* lin2_b  = (const float*)d_in[12];
    const float* lin3_w  = (const float*)d_in[13];
    const float* lin3_b  = (const float*)d_in[14];
    float* out = (float*)d_out;

    float *feat, *m1, *m2;
    fp16 *a0a, *a0l, *a1a, *a1l, *a2a, *a2l, *b0p, *bwp;
    cudaGetSymbolAddress((void**)&feat, g_feat);
    cudaGetSymbolAddress((void**)&m1, g_m1);
    cudaGetSymbolAddress((void**)&m2, g_m2);
    cudaGetSymbolAddress((void**)&a0a, g_A0a);
    cudaGetSymbolAddress((void**)&a0l, g_A0l);
    cudaGetSymbolAddress((void**)&a1a, g_A1a);
    cudaGetSymbolAddress((void**)&a1l, g_A1l);
    cudaGetSymbolAddress((void**)&a2a, g_A2a);
    cudaGetSymbolAddress((void**)&a2l, g_A2l);
    cudaGetSymbolAddress((void**)&b0p, g_B0);
    cudaGetSymbolAddress((void**)&bwp, g_Bw);

    cudaFuncSetAttribute(k_mmagemm, cudaFuncAttributeMaxDynamicSharedMemorySize,
                         2 * STAGE_B);
    const int dynsmem = 2 * STAGE_B;

    // CSR + graph segments
    k_zero_counts<<<(NN + 255) / 256, 256>>>();
    k_hist<<<(EE + 255) / 256, 256>>>(ei, batch);
    k_scan<<<1, 1024>>>();
    k_fill<<<(EE + 255) / 256, 256>>>(ei);
    k_sortadj<<<(NN + 127) / 128, 128>>>();

    // prep splits
    k_split_x<<<(NN * 64 + 255) / 256, 256>>>(x);
    k_split_w0<<<(HH * 128 + 255) / 256, 256>>>(w_root0, w_rel0);
    k_split_w<<<(4 * HH * 1024 + 255) / 256, 256>>>(w_root, w_rel);

    // layer 0: K'=128
    k_agg32<<<NN / 4, dim3(32, 4)>>>(x);
    k_mmagemm<<<dim3(HH / 128, NN / 128), 256, dynsmem>>>(
        a0a, a0l, b0p, b0, a1a, a1l, 128);

    // layers 1..4: K'=1024, ping-pong buf1/buf2
    fp16 *aca = a1a, *acl = a1l, *ana = a2a, *anl = a2l;
    for (int l = 0; l < 4; l++) {
        k_agg512<<<NN, 128>>>(aca, acl);
        k_mmagemm<<<dim3(HH / 128, NN / 128), 256, dynsmem>>>(
            aca, acl, bwp + (size_t)l * HH * 1024,
            bb + l * HH, ana, anl, 1024);
        fp16* t1 = aca; aca = ana; ana = t1;
        fp16* t2 = acl; acl = anl; anl = t2;
    }

    k_pool<<<dim3(GG, HH / 128), 128>>>(aca, acl);
    k_mlp<<<dim3(HH / 128, GG), 128>>>(feat, lin1_w, lin1_b, m1, 2 * HH, HH);
    k_mlp<<<dim3(HH / 128, GG), 128>>>(m1, lin2_w, lin2_b, m2, HH, HH);
    k_head<<<GG, 32>>>(m2, lin3_w, lin3_b, out);
}